// round 5
// baseline (speedup 1.0000x reference)
#include <cuda_runtime.h>
#include <cuda_bf16.h>
#include <cstdint>
#include <math.h>

#define D_MODEL 1024
#define D_STATE 16
#define DT_RANK 64
#define NBATCH 2
#define SEQ 2048
#define NROWS (NBATCH*SEQ)   // 4096
#define NC 64                // chunks per sequence
#define CT 32                // chunk length
#define NTOT 2176            // padded combined-N (2080 valid)

// ---------------- scratch (device globals) ---------------------------------
__device__ float g_xin [NROWS * D_MODEL];
__device__ float g_dt  [NROWS * D_MODEL];
__device__ float g_bc  [NROWS * 32];                 // B (0:16) | C (16:32)
__device__ float g_A   [D_MODEL * D_STATE];
__device__ float g_inp [NROWS * D_STATE];
__device__ float g_S   [NBATCH * NC * D_MODEL];
__device__ float g_L   [NBATCH * NC * D_MODEL * D_STATE];
__device__ float g_hs  [NBATCH * NC * D_MODEL * D_STATE];
// GEMM operands
__device__ __nv_bfloat16 g_xh [NROWS * D_MODEL];
__device__ __nv_bfloat16 g_xl [NROWS * D_MODEL];
__device__ __nv_bfloat16 g_wth[NTOT * D_MODEL];      // combined weight^T hi [n][k]
__device__ __nv_bfloat16 g_wtl[NTOT * D_MODEL];      // combined weight^T lo [n][k]
// weight-prep intermediates (fp32)
__device__ float g_P     [D_MODEL * 96];             // w_in @ w_x
__device__ float g_wdtpre[D_MODEL * D_MODEL];        // P[:, :64] @ w_dt

// ---------------- PTX helpers (family-portable) -----------------------------
__device__ __forceinline__ uint32_t smem_u32(const void* p) {
    uint32_t a;
    asm("{ .reg .u64 t; cvta.to.shared.u64 t, %1; cvt.u32.u64 %0, t; }"
        : "=r"(a) : "l"(p));
    return a;
}
__device__ __forceinline__ void cp16(uint32_t dst, const void* src) {
    asm volatile("cp.async.cg.shared.global [%0], [%1], 16;"
                 :: "r"(dst), "l"(src) : "memory");
}
#define CP_COMMIT() asm volatile("cp.async.commit_group;" ::: "memory")
#define CP_WAIT1()  asm volatile("cp.async.wait_group 1;" ::: "memory")
#define CP_WAIT0()  asm volatile("cp.async.wait_group 0;" ::: "memory")

#define LDSM4(r0,r1,r2,r3,addr) \
    asm volatile("ldmatrix.sync.aligned.m8n8.x4.shared.b16 {%0,%1,%2,%3}, [%4];" \
        : "=r"(r0),"=r"(r1),"=r"(r2),"=r"(r3) : "r"(addr))
#define LDSM2(r0,r1,addr) \
    asm volatile("ldmatrix.sync.aligned.m8n8.x2.shared.b16 {%0,%1}, [%2];" \
        : "=r"(r0),"=r"(r1) : "r"(addr))

#define MMA16816(d, a, b) \
    asm volatile("mma.sync.aligned.m16n8k16.row.col.f32.bf16.bf16.f32 " \
        "{%0,%1,%2,%3}, {%4,%5,%6,%7}, {%8,%9}, {%0,%1,%2,%3};" \
        : "+f"((d)[0]),"+f"((d)[1]),"+f"((d)[2]),"+f"((d)[3]) \
        : "r"((a)[0]),"r"((a)[1]),"r"((a)[2]),"r"((a)[3]), \
          "r"((b)[0]),"r"((b)[1]))

// ---------------- K_conv: split x into bf16 hi/lo; A = -exp(A_log) ----------
__global__ __launch_bounds__(256) void k_conv_x(const float* __restrict__ x,
                                                const float* __restrict__ A_log) {
    int i = blockIdx.x * blockDim.x + threadIdx.x;
    if (i < NROWS * D_MODEL) {
        float f = x[i];
        __nv_bfloat16 h = __float2bfloat16(f);
        g_xh[i] = h;
        g_xl[i] = __float2bfloat16(f - __bfloat162float(h));
    }
    if (i < D_MODEL * D_STATE) g_A[i] = -__expf(A_log[i]);
}

// ---------------- K_prep1: P = w_in(1024x1024) @ w_x(1024x96) ---------------
// BM=16, 64 CTAs, thread = (tm row, tn -> 6 cols)
__global__ __launch_bounds__(256) void k_prep1(const float* __restrict__ Win,
                                               const float* __restrict__ Wx) {
    __shared__ float As[32][16];
    __shared__ float Bs[32][96];
    int tid = threadIdx.x;
    int row0 = blockIdx.x * 16;
    int tm = tid >> 4, tn = tid & 15;
    float acc[6];
    #pragma unroll
    for (int j = 0; j < 6; j++) acc[j] = 0.f;

    for (int k0 = 0; k0 < D_MODEL; k0 += 32) {
        #pragma unroll
        for (int q = 0; q < 2; q++) {
            int idx = tid + q * 256;
            int m = idx >> 5, kk = idx & 31;
            As[kk][m] = Win[(row0 + m) * D_MODEL + k0 + kk];
        }
        #pragma unroll
        for (int q = 0; q < 3; q++) {
            int f4 = tid + q * 256;
            int kk = f4 / 24, cg = f4 % 24;
            float4 v = *(const float4*)(Wx + (k0 + kk) * 96 + cg * 4);
            *(float4*)&Bs[kk][cg * 4] = v;
        }
        __syncthreads();
        #pragma unroll
        for (int k = 0; k < 32; k++) {
            float a = As[k][tm];
            #pragma unroll
            for (int j = 0; j < 6; j++) acc[j] += a * Bs[k][tn * 6 + j];
        }
        __syncthreads();
    }
    #pragma unroll
    for (int j = 0; j < 6; j++)
        g_P[(row0 + tm) * 96 + tn * 6 + j] = acc[j];
}

// ---------------- K_prep2: Wdtpre = P[:, :64] @ w_dt(64x1024) ---------------
__global__ __launch_bounds__(256) void k_prep2(const float* __restrict__ Wdt) {
    __shared__ float As[64][65];
    __shared__ float Bs[64][64];
    int tid = threadIdx.x;
    int col0 = blockIdx.x * 64;
    int row0 = blockIdx.y * 64;

    #pragma unroll
    for (int q = 0; q < 16; q++) {
        int idx = tid + q * 256;
        int m = idx >> 6, kk = idx & 63;
        As[kk][m] = g_P[(row0 + m) * 96 + kk];
    }
    #pragma unroll
    for (int q = 0; q < 16; q++) {
        int idx = tid + q * 256;
        int kk = idx >> 6, n = idx & 63;
        Bs[kk][n] = Wdt[kk * D_MODEL + col0 + n];
    }
    __syncthreads();

    int tm = tid >> 4, tn = tid & 15;
    float acc[4][4];
    #pragma unroll
    for (int i = 0; i < 4; i++)
        #pragma unroll
        for (int j = 0; j < 4; j++) acc[i][j] = 0.f;

    #pragma unroll 16
    for (int k = 0; k < 64; k++) {
        float ra[4], rb[4];
        #pragma unroll
        for (int i = 0; i < 4; i++) ra[i] = As[k][tm * 4 + i];
        #pragma unroll
        for (int j = 0; j < 4; j++) rb[j] = Bs[k][tn * 4 + j];
        #pragma unroll
        for (int i = 0; i < 4; i++)
            #pragma unroll
            for (int j = 0; j < 4; j++) acc[i][j] += ra[i] * rb[j];
    }
    #pragma unroll
    for (int i = 0; i < 4; i++)
        #pragma unroll
        for (int j = 0; j < 4; j++)
            g_wdtpre[(row0 + tm * 4 + i) * D_MODEL + col0 + tn * 4 + j] = acc[i][j];
}

// ---------------- K_prep_w: build transposed hi/lo combined weight ----------
// source col n: [0,1024): w_in | [1024,2048): Wdtpre | [2048,2080): P[:,64:96] | pad 0
__global__ void k_prep_w(const float* __restrict__ Win) {
    __shared__ float t[32][33];
    int nb = blockIdx.x * 32, kb = blockIdx.y * 32;
    int tx = threadIdx.x, ty = threadIdx.y;   // 32 x 8
    #pragma unroll
    for (int i = 0; i < 32; i += 8) {
        int k = kb + ty + i, n = nb + tx;
        float v;
        if (n < 1024)        v = Win[k * D_MODEL + n];
        else if (n < 2048)   v = g_wdtpre[k * D_MODEL + (n - 1024)];
        else if (n < 2080)   v = g_P[k * 96 + 64 + (n - 2048)];
        else                 v = 0.f;
        t[ty + i][tx] = v;
    }
    __syncthreads();
    #pragma unroll
    for (int i = 0; i < 32; i += 8) {
        float f = t[tx][ty + i];              // src(k = kb+tx, n = nb+ty+i)
        __nv_bfloat16 h = __float2bfloat16(f);
        int n = nb + ty + i, k = kb + tx;
        g_wth[n * D_MODEL + k] = h;
        g_wtl[n * D_MODEL + k] = __float2bfloat16(f - __bfloat162float(h));
    }
}

// ---------------- K1: fused mma GEMM x(4096x1024) @ Wcomb(1024x2080) --------
// CTA tile 128x128, BK=16, double-buffered cp.async, 2 CTAs/SM.
// SMEM row stride 48B: bank-group start = 12r mod 32, conflict-free ldmatrix.
#define ROWB 48
#define TILE_B (128 * ROWB)          // 6144
#define STAGE_B (4 * TILE_B)         // 24576: Ah, Al, Bh, Bl
#define GEMM_SMEM (2 * STAGE_B)      // 49152
#define NT (D_MODEL / 16)            // 64 K-iterations

__global__ __launch_bounds__(256, 2) void k_gemm_mma(const float* __restrict__ bdt) {
    extern __shared__ char smem[];
    uint32_t sb = smem_u32(smem);
    int tid = threadIdx.x, wid = tid >> 5, lane = tid & 31;
    int n0 = blockIdx.x * 128, m0 = blockIdx.y * 128;
    int wm = wid >> 2, wn = wid & 3;       // 2 x 4 warp grid, warp tile 64x32

    const __nv_bfloat16* srcs[4] = {
        g_xh  + m0 * D_MODEL, g_xl  + m0 * D_MODEL,
        g_wth + n0 * D_MODEL, g_wtl + n0 * D_MODEL };

    int lr = tid >> 1, lc = tid & 1;       // load slot: row, 16B-chunk

    // prefetch stage 0
    #pragma unroll
    for (int tk = 0; tk < 4; tk++)
        cp16(sb + tk * TILE_B + lr * ROWB + lc * 16,
             srcs[tk] + lr * D_MODEL + lc * 8);
    CP_COMMIT();

    float acc[4][4][4];
    #pragma unroll
    for (int mf = 0; mf < 4; mf++)
        #pragma unroll
        for (int nf = 0; nf < 4; nf++)
            #pragma unroll
            for (int q = 0; q < 4; q++) acc[mf][nf][q] = 0.f;

    int aRow = wm * 64 + (lane & 15);
    int aOff = (lane >> 4) * 16;
    int bRow = wn * 32 + (lane & 7);
    int bOff = ((lane >> 3) & 1) * 16;

    for (int kt = 0; kt < NT; kt++) {
        if (kt + 1 < NT) {
            int k0 = (kt + 1) * 16;
            uint32_t stb = sb + ((kt + 1) & 1) * STAGE_B;
            #pragma unroll
            for (int tk = 0; tk < 4; tk++)
                cp16(stb + tk * TILE_B + lr * ROWB + lc * 16,
                     srcs[tk] + lr * D_MODEL + k0 + lc * 8);
            CP_COMMIT();
            CP_WAIT1();
        } else {
            CP_WAIT0();
        }
        __syncthreads();

        uint32_t stg = sb + (kt & 1) * STAGE_B;
        uint32_t Ah = stg, Al = stg + TILE_B;
        uint32_t Bh = stg + 2 * TILE_B, Bl = stg + 3 * TILE_B;

        uint32_t bh[4][2], bl[4][2];
        #pragma unroll
        for (int nf = 0; nf < 4; nf++) {
            uint32_t badr = (bRow + nf * 8) * ROWB + bOff;
            LDSM2(bh[nf][0], bh[nf][1], Bh + badr);
            LDSM2(bl[nf][0], bl[nf][1], Bl + badr);
        }
        #pragma unroll
        for (int mf = 0; mf < 4; mf++) {
            uint32_t aadr = (aRow + mf * 16) * ROWB + aOff;
            uint32_t ah[4], al[4];
            LDSM4(ah[0], ah[1], ah[2], ah[3], Ah + aadr);
            LDSM4(al[0], al[1], al[2], al[3], Al + aadr);
            #pragma unroll
            for (int nf = 0; nf < 4; nf++) {
                MMA16816(acc[mf][nf], ah, bh[nf]);
                MMA16816(acc[mf][nf], ah, bl[nf]);
                MMA16816(acc[mf][nf], al, bh[nf]);
            }
        }
        __syncthreads();
    }

    // epilogue with region routing
    int erow = m0 + wm * 64 + (lane >> 2);
    int ecol = n0 + wn * 32 + (lane & 3) * 2;
    #pragma unroll
    for (int mf = 0; mf < 4; mf++)
        #pragma unroll
        for (int nf = 0; nf < 4; nf++) {
            int col = ecol + nf * 8;
            #pragma unroll
            for (int half = 0; half < 2; half++) {
                int row = erow + mf * 16 + half * 8;
                float v0 = acc[mf][nf][half * 2 + 0];
                float v1 = acc[mf][nf][half * 2 + 1];
                if (col < 1024) {
                    *(float2*)(g_xin + row * D_MODEL + col) = make_float2(v0, v1);
                } else if (col < 2048) {
                    int c = col - 1024;
                    float z0 = v0 + bdt[c], z1 = v1 + bdt[c + 1];
                    float s0 = fmaxf(z0, 0.f) + log1pf(__expf(-fabsf(z0)));
                    float s1 = fmaxf(z1, 0.f) + log1pf(__expf(-fabsf(z1)));
                    *(float2*)(g_dt + row * D_MODEL + c) =
                        make_float2(s0 * 0.099f + 0.001f, s1 * 0.099f + 0.001f);
                } else if (col < 2080) {
                    int c = col - 2048;
                    *(float2*)(g_bc + row * 32 + c) = make_float2(v0, v1);
                }
            }
        }
}

// ---------------- K4: inp_term[r][n] = B[r][n] * sum_d dt*u*A[d][n] --------
__global__ __launch_bounds__(256) void k_inp() {
    int r = blockIdx.x;
    int tid = threadIdx.x;
    float acc[D_STATE];
    #pragma unroll
    for (int n = 0; n < D_STATE; n++) acc[n] = 0.f;

    const float* dtr = g_dt + r * D_MODEL;
    const float* ur  = g_xin + r * D_MODEL;
    for (int d = tid; d < D_MODEL; d += 256) {
        float w = dtr[d] * ur[d];
        const float4* Ap = (const float4*)(g_A + d * D_STATE);
        #pragma unroll
        for (int q = 0; q < 4; q++) {
            float4 a = Ap[q];
            acc[q * 4 + 0] += w * a.x;
            acc[q * 4 + 1] += w * a.y;
            acc[q * 4 + 2] += w * a.z;
            acc[q * 4 + 3] += w * a.w;
        }
    }
    #pragma unroll
    for (int n = 0; n < D_STATE; n++)
        #pragma unroll
        for (int off = 16; off > 0; off >>= 1)
            acc[n] += __shfl_xor_sync(0xFFFFFFFFu, acc[n], off);

    __shared__ float red[8][D_STATE];
    int warp = tid >> 5, lane = tid & 31;
    if (lane == 0)
        #pragma unroll
        for (int n = 0; n < D_STATE; n++) red[warp][n] = acc[n];
    __syncthreads();
    if (tid < D_STATE) {
        float s = 0.f;
        #pragma unroll
        for (int w = 0; w < 8; w++) s += red[w][tid];
        float Bm = g_bc[r * 32 + tid];
        g_inp[r * D_STATE + tid] = Bm * s;
    }
}

// ---------------- K5: scan phase A -----------------------------------------
__global__ __launch_bounds__(256) void k_scanA() {
    int blk = blockIdx.x;
    int dgrp = blk & 3;
    int c = (blk >> 2) & (NC - 1);
    int b = blk >> 8;
    int d = dgrp * 256 + threadIdx.x;
    int rbase = b * SEQ + c * CT;

    __shared__ float s_inp[CT * D_STATE];
    for (int i = threadIdx.x; i < CT * D_STATE; i += 256)
        s_inp[i] = g_inp[rbase * D_STATE + i];
    __syncthreads();

    float Ar[D_STATE];
    {
        const float4* Ap = (const float4*)(g_A + d * D_STATE);
        #pragma unroll
        for (int q = 0; q < 4; q++) {
            float4 a = Ap[q];
            Ar[q*4+0]=a.x; Ar[q*4+1]=a.y; Ar[q*4+2]=a.z; Ar[q*4+3]=a.w;
        }
    }
    float h[D_STATE];
    #pragma unroll
    for (int n = 0; n < D_STATE; n++) h[n] = 0.f;
    float S = 0.f;

    for (int t = 0; t < CT; t++) {
        float ldt = g_dt[(rbase + t) * D_MODEL + d];
        S += ldt;
        #pragma unroll
        for (int n = 0; n < D_STATE; n++)
            h[n] = __expf(ldt * Ar[n]) * h[n] + s_inp[t * D_STATE + n];
    }
    int base = (b * NC + c) * D_MODEL + d;
    g_S[base] = S;
    float* Lp = g_L + base * D_STATE;
    #pragma unroll
    for (int q = 0; q < 4; q++)
        ((float4*)Lp)[q] = make_float4(h[q*4+0], h[q*4+1], h[q*4+2], h[q*4+3]);
}

// ---------------- K6: scan phase B ------------------------------------------
__global__ __launch_bounds__(256) void k_scanB() {
    int idx = blockIdx.x * blockDim.x + threadIdx.x;
    int n = idx & (D_STATE - 1);
    int d = (idx >> 4) & (D_MODEL - 1);
    int b = idx >> 14;
    float a = g_A[d * D_STATE + n];
    float hs = 0.f;
    for (int c = 0; c < NC; c++) {
        int base = (b * NC + c) * D_MODEL + d;
        g_hs[base * D_STATE + n] = hs;
        hs = __expf(a * g_S[base]) * hs + g_L[base * D_STATE + n];
    }
}

// ---------------- K7: scan phase C ------------------------------------------
__global__ __launch_bounds__(256) void k_scanC(
    const float* __restrict__ Dp, float* __restrict__ out) {
    int blk = blockIdx.x;
    int dgrp = blk & 3;
    int c = (blk >> 2) & (NC - 1);
    int b = blk >> 8;
    int d = dgrp * 256 + threadIdx.x;
    int rbase = b * SEQ + c * CT;

    __shared__ float s_inp[CT * D_STATE];
    __shared__ float s_C[CT * D_STATE];
    for (int i = threadIdx.x; i < CT * D_STATE; i += 256) {
        int t = i >> 4;
        int n = i & (D_STATE - 1);
        s_inp[i] = g_inp[(rbase + t) * D_STATE + n];
        s_C[i]   = g_bc[(rbase + t) * 32 + 16 + n];
    }
    __syncthreads();

    float Ar[D_STATE], h[D_STATE];
    {
        const float4* Ap = (const float4*)(g_A + d * D_STATE);
        #pragma unroll
        for (int q = 0; q < 4; q++) {
            float4 a = Ap[q];
            Ar[q*4+0]=a.x; Ar[q*4+1]=a.y; Ar[q*4+2]=a.z; Ar[q*4+3]=a.w;
        }
        int base = (b * NC + c) * D_MODEL + d;
        const float4* Hp = (const float4*)(g_hs + base * D_STATE);
        #pragma unroll
        for (int q = 0; q < 4; q++) {
            float4 v = Hp[q];
            h[q*4+0]=v.x; h[q*4+1]=v.y; h[q*4+2]=v.z; h[q*4+3]=v.w;
        }
    }
    float dp = Dp[d];

    for (int t = 0; t < CT; t++) {
        int r = rbase + t;
        float ldt = g_dt[r * D_MODEL + d];
        float u   = g_xin[r * D_MODEL + d];
        float y = dp * u;
        #pragma unroll
        for (int n = 0; n < D_STATE; n++) {
            h[n] = __expf(ldt * Ar[n]) * h[n] + s_inp[t * D_STATE + n];
            y += h[n] * s_C[t * D_STATE + n];
        }
        out[r * D_MODEL + d] = y;
    }
}

// ---------------- launch ----------------------------------------------------
extern "C" void kernel_launch(void* const* d_in, const int* in_sizes, int n_in,
                              void* d_out, int out_size) {
    const float* x     = (const float*)d_in[0];
    const float* w_in  = (const float*)d_in[1];
    const float* w_x   = (const float*)d_in[2];
    const float* w_dt  = (const float*)d_in[3];
    const float* b_dt  = (const float*)d_in[4];
    const float* A_log = (const float*)d_in[5];
    const float* Dp    = (const float*)d_in[6];
    float* out = (float*)d_out;

    cudaFuncSetAttribute(k_gemm_mma, cudaFuncAttributeMaxDynamicSharedMemorySize,
                         GEMM_SMEM);

    k_conv_x<<<(NROWS * D_MODEL + 255) / 256, 256>>>(x, A_log);
    k_prep1<<<64, 256>>>(w_in, w_x);
    k_prep2<<<dim3(16, 16), 256>>>(w_dt);
    k_prep_w<<<dim3(NTOT / 32, D_MODEL / 32), dim3(32, 8)>>>(w_in);
    k_gemm_mma<<<dim3(NTOT / 128, NROWS / 128), 256, GEMM_SMEM>>>(b_dt);
    k_inp<<<NROWS, 256>>>();
    k_scanA<<<NBATCH * NC * 4, 256>>>();
    k_scanB<<<NBATCH * D_MODEL * D_STATE / 256, 256>>>();
    k_scanC<<<NBATCH * NC * 4, 256>>>(Dp, out);
}

// round 6
// speedup vs baseline: 1.3677x; 1.3677x over previous
#include <cuda_runtime.h>
#include <cuda_bf16.h>
#include <cstdint>
#include <math.h>

#define D_MODEL 1024
#define D_STATE 16
#define DT_RANK 64
#define NBATCH 2
#define SEQ 2048
#define NROWS (NBATCH*SEQ)   // 4096
#define NPROJ 96
#define NC 64                // chunks per sequence
#define CT 32                // chunk length
#define NTOT 1152            // 1024 (w_in) + 96 (P) + 32 pad

// ---------------- scratch (device globals) ---------------------------------
__device__ float g_xin [NROWS * D_MODEL];
__device__ float g_proj[NROWS * NPROJ];              // dt_low | B | C
__device__ float g_dt  [NROWS * D_MODEL];
__device__ float g_A   [D_MODEL * D_STATE];
__device__ float g_inp [NROWS * D_STATE];
__device__ float g_S   [NBATCH * NC * D_MODEL];
__device__ float g_L   [NBATCH * NC * D_MODEL * D_STATE];
__device__ float g_hs  [NBATCH * NC * D_MODEL * D_STATE];
// GEMM operands
__device__ __nv_bfloat16 g_xh [NROWS * D_MODEL];
__device__ __nv_bfloat16 g_xl [NROWS * D_MODEL];
__device__ __nv_bfloat16 g_wth[NTOT * D_MODEL];      // [w_in | P]^T hi  [n][k]
__device__ __nv_bfloat16 g_wtl[NTOT * D_MODEL];      // [w_in | P]^T lo  [n][k]
__device__ float g_P   [D_MODEL * NPROJ];            // w_in @ w_x

// ---------------- PTX helpers (family-portable) -----------------------------
__device__ __forceinline__ uint32_t smem_u32(const void* p) {
    uint32_t a;
    asm("{ .reg .u64 t; cvta.to.shared.u64 t, %1; cvt.u32.u64 %0, t; }"
        : "=r"(a) : "l"(p));
    return a;
}
__device__ __forceinline__ void cp16(uint32_t dst, const void* src) {
    asm volatile("cp.async.cg.shared.global [%0], [%1], 16;"
                 :: "r"(dst), "l"(src) : "memory");
}
#define CP_COMMIT() asm volatile("cp.async.commit_group;" ::: "memory")
#define CP_WAIT1()  asm volatile("cp.async.wait_group 1;" ::: "memory")
#define CP_WAIT0()  asm volatile("cp.async.wait_group 0;" ::: "memory")

#define LDSM4(r0,r1,r2,r3,addr) \
    asm volatile("ldmatrix.sync.aligned.m8n8.x4.shared.b16 {%0,%1,%2,%3}, [%4];" \
        : "=r"(r0),"=r"(r1),"=r"(r2),"=r"(r3) : "r"(addr))
#define LDSM2(r0,r1,addr) \
    asm volatile("ldmatrix.sync.aligned.m8n8.x2.shared.b16 {%0,%1}, [%2];" \
        : "=r"(r0),"=r"(r1) : "r"(addr))

#define MMA16816(d, a, b) \
    asm volatile("mma.sync.aligned.m16n8k16.row.col.f32.bf16.bf16.f32 " \
        "{%0,%1,%2,%3}, {%4,%5,%6,%7}, {%8,%9}, {%0,%1,%2,%3};" \
        : "+f"((d)[0]),"+f"((d)[1]),"+f"((d)[2]),"+f"((d)[3]) \
        : "r"((a)[0]),"r"((a)[1]),"r"((a)[2]),"r"((a)[3]), \
          "r"((b)[0]),"r"((b)[1]))

// ---------------- K_conv: split x into bf16 hi/lo; A = -exp(A_log) ----------
__global__ __launch_bounds__(256) void k_conv_x(const float* __restrict__ x,
                                                const float* __restrict__ A_log) {
    int i = blockIdx.x * blockDim.x + threadIdx.x;
    if (i < NROWS * D_MODEL) {
        float f = x[i];
        __nv_bfloat16 h = __float2bfloat16(f);
        g_xh[i] = h;
        g_xl[i] = __float2bfloat16(f - __bfloat162float(h));
    }
    if (i < D_MODEL * D_STATE) g_A[i] = -__expf(A_log[i]);
}

// ---------------- K_prep1: P = w_in(1024x1024) @ w_x(1024x96) ---------------
__global__ __launch_bounds__(256) void k_prep1(const float* __restrict__ Win,
                                               const float* __restrict__ Wx) {
    __shared__ float As[32][16];
    __shared__ float Bs[32][96];
    int tid = threadIdx.x;
    int row0 = blockIdx.x * 16;
    int tm = tid >> 4, tn = tid & 15;
    float acc[6];
    #pragma unroll
    for (int j = 0; j < 6; j++) acc[j] = 0.f;

    for (int k0 = 0; k0 < D_MODEL; k0 += 32) {
        #pragma unroll
        for (int q = 0; q < 2; q++) {
            int idx = tid + q * 256;
            int m = idx >> 5, kk = idx & 31;
            As[kk][m] = Win[(row0 + m) * D_MODEL + k0 + kk];
        }
        #pragma unroll
        for (int q = 0; q < 3; q++) {
            int f4 = tid + q * 256;
            int kk = f4 / 24, cg = f4 % 24;
            float4 v = *(const float4*)(Wx + (k0 + kk) * NPROJ + cg * 4);
            *(float4*)&Bs[kk][cg * 4] = v;
        }
        __syncthreads();
        #pragma unroll
        for (int k = 0; k < 32; k++) {
            float a = As[k][tm];
            #pragma unroll
            for (int j = 0; j < 6; j++) acc[j] += a * Bs[k][tn * 6 + j];
        }
        __syncthreads();
    }
    #pragma unroll
    for (int j = 0; j < 6; j++)
        g_P[(row0 + tm) * NPROJ + tn * 6 + j] = acc[j];
}

// ---------------- K_prep_w: transpose+split [w_in | P | 0] -> hi/lo ---------
__global__ void k_prep_w(const float* __restrict__ Win) {
    __shared__ float t[32][33];
    int nb = blockIdx.x * 32, kb = blockIdx.y * 32;
    int tx = threadIdx.x, ty = threadIdx.y;   // 32 x 8
    #pragma unroll
    for (int i = 0; i < 32; i += 8) {
        int k = kb + ty + i, n = nb + tx;
        float v;
        if (n < 1024)      v = Win[k * D_MODEL + n];
        else if (n < 1120) v = g_P[k * NPROJ + (n - 1024)];
        else               v = 0.f;
        t[ty + i][tx] = v;
    }
    __syncthreads();
    #pragma unroll
    for (int i = 0; i < 32; i += 8) {
        float f = t[tx][ty + i];
        __nv_bfloat16 h = __float2bfloat16(f);
        int n = nb + ty + i, k = kb + tx;
        g_wth[n * D_MODEL + k] = h;
        g_wtl[n * D_MODEL + k] = __float2bfloat16(f - __bfloat162float(h));
    }
}

// ---------------- K1: mma GEMM x(4096x1024) @ [w_in|P](1024x1120) -----------
// CTA 128x128, BK=32, double-buffered cp.async, 2 CTAs/SM.
#define ROWB 80
#define TILE_B (128 * ROWB)          // 10240
#define STAGE_B (4 * TILE_B)         // 40960
#define GEMM_SMEM (2 * STAGE_B)      // 81920
#define NT (D_MODEL / 32)            // 32 K-iterations

__global__ __launch_bounds__(256, 2) void k_gemm_mma() {
    extern __shared__ char smem[];
    uint32_t sb = smem_u32(smem);
    int tid = threadIdx.x, wid = tid >> 5, lane = tid & 31;
    int n0 = blockIdx.x * 128, m0 = blockIdx.y * 128;
    int wm = wid >> 2, wn = wid & 3;       // 2x4 warps, warp tile 64x32

    const __nv_bfloat16* srcs[4] = {
        g_xh  + m0 * D_MODEL, g_xl  + m0 * D_MODEL,
        g_wth + n0 * D_MODEL, g_wtl + n0 * D_MODEL };

    int ch0 = tid, ch1 = tid + 256;
    int r0 = ch0 >> 2, c0 = ch0 & 3;
    int r1 = ch1 >> 2, c1 = ch1 & 3;

    #pragma unroll
    for (int tk = 0; tk < 4; tk++) {
        uint32_t tb = sb + tk * TILE_B;
        cp16(tb + r0 * ROWB + c0 * 16, srcs[tk] + r0 * D_MODEL + c0 * 8);
        cp16(tb + r1 * ROWB + c1 * 16, srcs[tk] + r1 * D_MODEL + c1 * 8);
    }
    CP_COMMIT();

    float acc[4][4][4];
    #pragma unroll
    for (int mf = 0; mf < 4; mf++)
        #pragma unroll
        for (int nf = 0; nf < 4; nf++)
            #pragma unroll
            for (int q = 0; q < 4; q++) acc[mf][nf][q] = 0.f;

    int aRow = wm * 64 + (lane & 15);
    int aOff = (lane >> 4) * 16;
    int bRow = wn * 32 + (lane & 7);
    int bOff = ((lane >> 3) & 1) * 16;

    for (int kt = 0; kt < NT; kt++) {
        if (kt + 1 < NT) {
            int k0 = (kt + 1) * 32;
            uint32_t stb = sb + ((kt + 1) & 1) * STAGE_B;
            #pragma unroll
            for (int tk = 0; tk < 4; tk++) {
                uint32_t tb = stb + tk * TILE_B;
                cp16(tb + r0 * ROWB + c0 * 16, srcs[tk] + r0 * D_MODEL + k0 + c0 * 8);
                cp16(tb + r1 * ROWB + c1 * 16, srcs[tk] + r1 * D_MODEL + k0 + c1 * 8);
            }
            CP_COMMIT();
            CP_WAIT1();
        } else {
            CP_WAIT0();
        }
        __syncthreads();

        uint32_t stg = sb + (kt & 1) * STAGE_B;
        uint32_t Ah = stg, Al = stg + TILE_B;
        uint32_t Bh = stg + 2 * TILE_B, Bl = stg + 3 * TILE_B;

        #pragma unroll
        for (int ks = 0; ks < 2; ks++) {
            uint32_t bh[4][2], bl[4][2];
            #pragma unroll
            for (int nf = 0; nf < 4; nf++) {
                uint32_t badr = (bRow + nf * 8) * ROWB + ks * 32 + bOff;
                LDSM2(bh[nf][0], bh[nf][1], Bh + badr);
                LDSM2(bl[nf][0], bl[nf][1], Bl + badr);
            }
            #pragma unroll
            for (int mf = 0; mf < 4; mf++) {
                uint32_t aadr = (aRow + mf * 16) * ROWB + ks * 32 + aOff;
                uint32_t ah[4], al[4];
                LDSM4(ah[0], ah[1], ah[2], ah[3], Ah + aadr);
                LDSM4(al[0], al[1], al[2], al[3], Al + aadr);
                #pragma unroll
                for (int nf = 0; nf < 4; nf++) {
                    MMA16816(acc[mf][nf], ah, bh[nf]);
                    MMA16816(acc[mf][nf], ah, bl[nf]);
                    MMA16816(acc[mf][nf], al, bh[nf]);
                }
            }
        }
        __syncthreads();
    }

    // epilogue: route col<1024 -> g_xin; [1024,1120) -> g_proj; else drop
    int erow = m0 + wm * 64 + (lane >> 2);
    int ecol = n0 + wn * 32 + (lane & 3) * 2;
    #pragma unroll
    for (int mf = 0; mf < 4; mf++)
        #pragma unroll
        for (int nf = 0; nf < 4; nf++) {
            int col = ecol + nf * 8;
            #pragma unroll
            for (int half = 0; half < 2; half++) {
                int row = erow + mf * 16 + half * 8;
                float v0 = acc[mf][nf][half * 2 + 0];
                float v1 = acc[mf][nf][half * 2 + 1];
                if (col < 1024) {
                    *(float2*)(g_xin + row * D_MODEL + col) = make_float2(v0, v1);
                } else if (col < 1120) {
                    *(float2*)(g_proj + row * NPROJ + (col - 1024)) =
                        make_float2(v0, v1);
                }
            }
        }
}

// ---------------- K3: dt = softplus(dt_low @ w_dt + b_dt)*0.099+0.001 ------
__global__ __launch_bounds__(256) void k_gemm_dt(
    const float* __restrict__ Wdt, const float* __restrict__ bdt) {
    __shared__ float As[64][65];
    __shared__ float Bs[64][64];
    int tid = threadIdx.x;
    int col0 = blockIdx.x * 64;
    int row0 = blockIdx.y * 64;

    #pragma unroll
    for (int q = 0; q < 16; q++) {
        int idx = tid + q * 256;
        int m = idx >> 6, kk = idx & 63;
        As[kk][m] = g_proj[(row0 + m) * NPROJ + kk];
    }
    #pragma unroll
    for (int q = 0; q < 16; q++) {
        int idx = tid + q * 256;
        int kk = idx >> 6, n = idx & 63;
        Bs[kk][n] = Wdt[kk * D_MODEL + col0 + n];
    }
    __syncthreads();

    int tm = tid >> 4, tn = tid & 15;
    float acc[4][4];
    #pragma unroll
    for (int i = 0; i < 4; i++)
        #pragma unroll
        for (int j = 0; j < 4; j++) acc[i][j] = 0.f;

    #pragma unroll 16
    for (int k = 0; k < 64; k++) {
        float ra[4], rb[4];
        #pragma unroll
        for (int i = 0; i < 4; i++) ra[i] = As[k][tm * 4 + i];
        #pragma unroll
        for (int j = 0; j < 4; j++) rb[j] = Bs[k][tn * 4 + j];
        #pragma unroll
        for (int i = 0; i < 4; i++)
            #pragma unroll
            for (int j = 0; j < 4; j++) acc[i][j] += ra[i] * rb[j];
    }
    #pragma unroll
    for (int i = 0; i < 4; i++)
        #pragma unroll
        for (int j = 0; j < 4; j++) {
            int col = col0 + tn * 4 + j;
            float z = acc[i][j] + bdt[col];
            float sp = fmaxf(z, 0.f) + log1pf(__expf(-fabsf(z)));
            g_dt[(row0 + tm * 4 + i) * D_MODEL + col] = sp * 0.099f + 0.001f;
        }
}

// ---------------- K4: inp_term[r][n] = B[r][n] * sum_d dt*u*A[d][n] --------
__global__ __launch_bounds__(256) void k_inp() {
    int r = blockIdx.x;
    int tid = threadIdx.x;
    float acc[D_STATE];
    #pragma unroll
    for (int n = 0; n < D_STATE; n++) acc[n] = 0.f;

    const float* dtr = g_dt + r * D_MODEL;
    const float* ur  = g_xin + r * D_MODEL;
    for (int d = tid; d < D_MODEL; d += 256) {
        float w = dtr[d] * ur[d];
        const float4* Ap = (const float4*)(g_A + d * D_STATE);
        #pragma unroll
        for (int q = 0; q < 4; q++) {
            float4 a = Ap[q];
            acc[q * 4 + 0] += w * a.x;
            acc[q * 4 + 1] += w * a.y;
            acc[q * 4 + 2] += w * a.z;
            acc[q * 4 + 3] += w * a.w;
        }
    }
    #pragma unroll
    for (int n = 0; n < D_STATE; n++)
        #pragma unroll
        for (int off = 16; off > 0; off >>= 1)
            acc[n] += __shfl_xor_sync(0xFFFFFFFFu, acc[n], off);

    __shared__ float red[8][D_STATE];
    int warp = tid >> 5, lane = tid & 31;
    if (lane == 0)
        #pragma unroll
        for (int n = 0; n < D_STATE; n++) red[warp][n] = acc[n];
    __syncthreads();
    if (tid < D_STATE) {
        float s = 0.f;
        #pragma unroll
        for (int w = 0; w < 8; w++) s += red[w][tid];
        float Bm = g_proj[r * NPROJ + DT_RANK + tid];
        g_inp[r * D_STATE + tid] = Bm * s;
    }
}

// ---------------- K5: scan phase A -----------------------------------------
__global__ __launch_bounds__(256) void k_scanA() {
    int blk = blockIdx.x;
    int dgrp = blk & 3;
    int c = (blk >> 2) & (NC - 1);
    int b = blk >> 8;
    int d = dgrp * 256 + threadIdx.x;
    int rbase = b * SEQ + c * CT;

    __shared__ float s_inp[CT * D_STATE];
    for (int i = threadIdx.x; i < CT * D_STATE; i += 256)
        s_inp[i] = g_inp[rbase * D_STATE + i];
    __syncthreads();

    float Ar[D_STATE];
    {
        const float4* Ap = (const float4*)(g_A + d * D_STATE);
        #pragma unroll
        for (int q = 0; q < 4; q++) {
            float4 a = Ap[q];
            Ar[q*4+0]=a.x; Ar[q*4+1]=a.y; Ar[q*4+2]=a.z; Ar[q*4+3]=a.w;
        }
    }
    float h[D_STATE];
    #pragma unroll
    for (int n = 0; n < D_STATE; n++) h[n] = 0.f;
    float S = 0.f;

    for (int t = 0; t < CT; t++) {
        float ldt = g_dt[(rbase + t) * D_MODEL + d];
        S += ldt;
        #pragma unroll
        for (int n = 0; n < D_STATE; n++)
            h[n] = __expf(ldt * Ar[n]) * h[n] + s_inp[t * D_STATE + n];
    }
    int base = (b * NC + c) * D_MODEL + d;
    g_S[base] = S;
    float* Lp = g_L + base * D_STATE;
    #pragma unroll
    for (int q = 0; q < 4; q++)
        ((float4*)Lp)[q] = make_float4(h[q*4+0], h[q*4+1], h[q*4+2], h[q*4+3]);
}

// ---------------- K6: scan phase B ------------------------------------------
__global__ __launch_bounds__(256) void k_scanB() {
    int idx = blockIdx.x * blockDim.x + threadIdx.x;
    int n = idx & (D_STATE - 1);
    int d = (idx >> 4) & (D_MODEL - 1);
    int b = idx >> 14;
    float a = g_A[d * D_STATE + n];
    float hs = 0.f;
    for (int c = 0; c < NC; c++) {
        int base = (b * NC + c) * D_MODEL + d;
        g_hs[base * D_STATE + n] = hs;
        hs = __expf(a * g_S[base]) * hs + g_L[base * D_STATE + n];
    }
}

// ---------------- K7: scan phase C ------------------------------------------
__global__ __launch_bounds__(256) void k_scanC(
    const float* __restrict__ Dp, float* __restrict__ out) {
    int blk = blockIdx.x;
    int dgrp = blk & 3;
    int c = (blk >> 2) & (NC - 1);
    int b = blk >> 8;
    int d = dgrp * 256 + threadIdx.x;
    int rbase = b * SEQ + c * CT;

    __shared__ float s_inp[CT * D_STATE];
    __shared__ float s_C[CT * D_STATE];
    for (int i = threadIdx.x; i < CT * D_STATE; i += 256) {
        int t = i >> 4;
        int n = i & (D_STATE - 1);
        s_inp[i] = g_inp[(rbase + t) * D_STATE + n];
        s_C[i]   = g_proj[(rbase + t) * NPROJ + DT_RANK + D_STATE + n];
    }
    __syncthreads();

    float Ar[D_STATE], h[D_STATE];
    {
        const float4* Ap = (const float4*)(g_A + d * D_STATE);
        #pragma unroll
        for (int q = 0; q < 4; q++) {
            float4 a = Ap[q];
            Ar[q*4+0]=a.x; Ar[q*4+1]=a.y; Ar[q*4+2]=a.z; Ar[q*4+3]=a.w;
        }
        int base = (b * NC + c) * D_MODEL + d;
        const float4* Hp = (const float4*)(g_hs + base * D_STATE);
        #pragma unroll
        for (int q = 0; q < 4; q++) {
            float4 v = Hp[q];
            h[q*4+0]=v.x; h[q*4+1]=v.y; h[q*4+2]=v.z; h[q*4+3]=v.w;
        }
    }
    float dp = Dp[d];

    for (int t = 0; t < CT; t++) {
        int r = rbase + t;
        float ldt = g_dt[r * D_MODEL + d];
        float u   = g_xin[r * D_MODEL + d];
        float y = dp * u;
        #pragma unroll
        for (int n = 0; n < D_STATE; n++) {
            h[n] = __expf(ldt * Ar[n]) * h[n] + s_inp[t * D_STATE + n];
            y += h[n] * s_C[t * D_STATE + n];
        }
        out[r * D_MODEL + d] = y;
    }
}

// ---------------- launch ----------------------------------------------------
extern "C" void kernel_launch(void* const* d_in, const int* in_sizes, int n_in,
                              void* d_out, int out_size) {
    const float* x     = (const float*)d_in[0];
    const float* w_in  = (const float*)d_in[1];
    const float* w_x   = (const float*)d_in[2];
    const float* w_dt  = (const float*)d_in[3];
    const float* b_dt  = (const float*)d_in[4];
    const float* A_log = (const float*)d_in[5];
    const float* Dp    = (const float*)d_in[6];
    float* out = (float*)d_out;

    cudaFuncSetAttribute(k_gemm_mma, cudaFuncAttributeMaxDynamicSharedMemorySize,
                         GEMM_SMEM);

    k_conv_x<<<(NROWS * D_MODEL + 255) / 256, 256>>>(x, A_log);
    k_prep1<<<64, 256>>>(w_in, w_x);
    k_prep_w<<<dim3(NTOT / 32, D_MODEL / 32), dim3(32, 8)>>>(w_in);
    k_gemm_mma<<<dim3(NTOT / 128, NROWS / 128), 256, GEMM_SMEM>>>();
    k_gemm_dt<<<dim3(D_MODEL / 64, NROWS / 64), 256>>>(w_dt, b_dt);
    k_inp<<<NROWS, 256>>>();
    k_scanA<<<NBATCH * NC * 4, 256>>>();
    k_scanB<<<NBATCH * D_MODEL * D_STATE / 256, 256>>>();
    k_scanC<<<NBATCH * NC * 4, 256>>>(Dp, out);
}